// round 3
// baseline (speedup 1.0000x reference)
#include <cuda_runtime.h>
#include <cstdint>

#define HID 128
#define T_STEPS 2048
#define BATCH 64
#define NOUT 5
#define MROWS (BATCH * T_STEPS)   // 131072

// -------------------- scratch (device globals; no allocation) --------------------
__device__ float g_xw[(size_t)MROWS * 384];   // input-projection buffer
__device__ float g_h0[(size_t)MROWS * HID];   // layer output ping
__device__ float g_h1[(size_t)MROWS * HID];   // layer output pong

// -------------------- packed f32x2 helpers --------------------
__device__ __forceinline__ unsigned long long pack2(float lo, float hi) {
    unsigned long long r;
    asm("mov.b64 %0, {%1, %2};" : "=l"(r) : "f"(lo), "f"(hi));
    return r;
}
__device__ __forceinline__ void unpack2(unsigned long long v, float& lo, float& hi) {
    asm("mov.b64 {%0, %1}, %2;" : "=f"(lo), "=f"(hi) : "l"(v));
}
#define FMA2(d, a, b, c) \
    asm("fma.rn.f32x2 %0, %1, %2, %3;" : "=l"(d) : "l"(a), "l"(b), "l"(c))

// ============================================================================
// GEMM: C[M,384-tile] = A[M,128] @ W[128,384] + bias_in (+ brec for cols<256)
// grid = (M/128, 3), 256 threads, dynamic smem = As(128x132) + Bs(128x128)
// Folding brec into the z,r columns lets the scan tail skip those bias adds.
// ============================================================================
__global__ __launch_bounds__(256, 1)
void gemm128(const float* __restrict__ A, const float* __restrict__ W,
             const float* __restrict__ bias, const float* __restrict__ brec,
             float* __restrict__ C, int M) {
    extern __shared__ float smem[];
    float* As = smem;              // As[k][m], pitch 132
    float* Bs = smem + 128 * 132;  // Bs[k][n], pitch 128

    const int m0 = blockIdx.x * 128;
    const int n0 = blockIdx.y * 128;
    const int tid = threadIdx.x;

    for (int idx = tid; idx < 128 * 32; idx += 256) {
        int r = idx >> 5, c4 = idx & 31;
        float4 v = *(const float4*)(A + (size_t)(m0 + r) * 128 + c4 * 4);
        As[(c4 * 4 + 0) * 132 + r] = v.x;
        As[(c4 * 4 + 1) * 132 + r] = v.y;
        As[(c4 * 4 + 2) * 132 + r] = v.z;
        As[(c4 * 4 + 3) * 132 + r] = v.w;
    }
    for (int idx = tid; idx < 128 * 32; idx += 256) {
        int k = idx >> 5, c4 = idx & 31;
        *(float4*)&Bs[k * 128 + c4 * 4] =
            *(const float4*)(W + (size_t)k * 384 + n0 + c4 * 4);
    }
    __syncthreads();

    const int tx = tid & 15, ty = tid >> 4;
    const int mr = ty * 8, nc = tx * 8;

    unsigned long long acc[8][4];
#pragma unroll
    for (int i = 0; i < 8; i++)
#pragma unroll
        for (int jj = 0; jj < 4; jj++) acc[i][jj] = 0ULL;

#pragma unroll 8
    for (int k = 0; k < 128; k++) {
        float4 a0 = *(const float4*)&As[k * 132 + mr];
        float4 a1 = *(const float4*)&As[k * 132 + mr + 4];
        ulonglong2 b0 = *(const ulonglong2*)&Bs[k * 128 + nc];
        ulonglong2 b1 = *(const ulonglong2*)&Bs[k * 128 + nc + 4];
        float av[8] = {a0.x, a0.y, a0.z, a0.w, a1.x, a1.y, a1.z, a1.w};
        unsigned long long bp[4] = {b0.x, b0.y, b1.x, b1.y};
#pragma unroll
        for (int i = 0; i < 8; i++) {
            unsigned long long ap = pack2(av[i], av[i]);
#pragma unroll
            for (int jj = 0; jj < 4; jj++) FMA2(acc[i][jj], ap, bp[jj], acc[i][jj]);
        }
    }

    float bv[8];
#pragma unroll
    for (int c = 0; c < 8; c++) {
        int n = n0 + nc + c;
        bv[c] = bias[n] + (n < 256 ? brec[n] : 0.0f);
    }

#pragma unroll
    for (int i = 0; i < 8; i++) {
        float o[8];
#pragma unroll
        for (int jj = 0; jj < 4; jj++) unpack2(acc[i][jj], o[2 * jj], o[2 * jj + 1]);
#pragma unroll
        for (int c = 0; c < 8; c++) o[c] += bv[c];
        float* cp = C + (size_t)(m0 + mr + i) * 384 + n0 + nc;
        *(float4*)cp = make_float4(o[0], o[1], o[2], o[3]);
        *(float4*)(cp + 4) = make_float4(o[4], o[5], o[6], o[7]);
    }
}

// ============================================================================
// GRU scan v3: one CTA/batch, 768 threads, split-K by 2.
//  thread tid: half = tid>=384, j = tid - half*384 owns rk[64*half:64*half+64, j]
//  -> only 64 weight regs/thread; 24 warps (6/SMSP) hide LDS latency.
//  Partials combined + activations on tid<128 only (1 warp/SMSP; MUFU rt=8).
//  x-part and z/r biases pre-folded; h kept in tail registers.
// ============================================================================
__global__ __launch_bounds__(768, 1)
void scan_kernel(const float* __restrict__ xw, const float* __restrict__ rk,
                 const float* __restrict__ brec, float* __restrict__ hout) {
    const int b = blockIdx.x;
    const int tid = threadIdx.x;
    const int half = (tid >= 384) ? 1 : 0;
    const int j = tid - half * 384;

    __shared__ __align__(16) float h_sh[HID];
    __shared__ float g_part[768];
    __shared__ float xh_sh[HID];

    // 64 weights (rows 64*half .. 64*half+63 of column j) as 32 f32x2 pairs
    unsigned long long w2[32];
    {
        const float* rkc = rk + (size_t)(64 * half) * 384 + j;
#pragma unroll
        for (int i = 0; i < 32; i++) {
            float a0 = rkc[(size_t)(2 * i) * 384];
            float a1 = rkc[(size_t)(2 * i + 1) * 384];
            w2[i] = pack2(a0, a1);
        }
    }

    const float brh = (tid < HID) ? brec[256 + tid] : 0.0f;  // h-gate rec bias (tail only)
    float h_reg = 0.0f;                                      // tail-owned h[tid]

    if (tid < HID) h_sh[tid] = 0.0f;
    const float* xrow = xw + (size_t)b * T_STEPS * 384 + j;
    float xv0 = xrow[0];
    float xv1 = xrow[384];
    float* hrow = hout + (size_t)b * T_STEPS * HID + tid;  // valid for tid<128
    __syncthreads();

    for (int t = 0; t < T_STEPS; t++) {
        int tp = t + 2 < T_STEPS ? t + 2 : T_STEPS - 1;
        float xv2 = xrow[(size_t)tp * 384];

        // half-dot: 16 LDS.128 (broadcast) + 32 FMA2, two dependency chains
        const ulonglong2* hp = (const ulonglong2*)h_sh + half * 16;
        unsigned long long a0 = 0ULL, a1 = 0ULL;
#pragma unroll
        for (int i = 0; i < 16; i++) {
            ulonglong2 u = hp[i];
            FMA2(a0, u.x, w2[2 * i], a0);
            FMA2(a1, u.y, w2[2 * i + 1], a1);
        }
        float l0, h0f, l1, h1f;
        unpack2(a0, l0, h0f);
        unpack2(a1, l1, h1f);
        float part = (l0 + l1) + (h0f + h1f);

        if (half == 0) {
            if (j < 256) part += xv0;       // z,r: fold x-part (biases already in xw)
            else xh_sh[j - 256] = xv0;      // h-gate x-part kept separate
        }
        g_part[tid] = part;
        __syncthreads();

        if (tid < HID) {
            float gz = g_part[tid] + g_part[384 + tid];
            float gr = g_part[128 + tid] + g_part[512 + tid];
            float ph = g_part[256 + tid] + g_part[640 + tid] + brh;
            float xh = xh_sh[tid];
            float z = __fdividef(1.0f, 1.0f + __expf(-gz));
            float r = __fdividef(1.0f, 1.0f + __expf(-gr));
            float e2 = __expf(-2.0f * (xh + r * ph));
            float hh = __fdividef(2.0f, 1.0f + e2) - 1.0f;   // tanh
            float hn = z * h_reg + (1.0f - z) * hh;
            h_reg = hn;
            h_sh[tid] = hn;
            hrow[(size_t)t * HID] = hn;
        }
        __syncthreads();

        xv0 = xv1;
        xv1 = xv2;
    }
}

// ============================================================================
// Output head: out[M,5] = H[M,128] @ wo[128,5] + bo
// ============================================================================
__global__ __launch_bounds__(256, 1)
void outproj(const float* __restrict__ H, const float* __restrict__ wo,
             const float* __restrict__ bo, float* __restrict__ out, int M) {
    __shared__ float ws[HID * NOUT];
    __shared__ float bs[NOUT];
    for (int i = threadIdx.x; i < HID * NOUT; i += blockDim.x) ws[i] = wo[i];
    if (threadIdx.x < NOUT) bs[threadIdx.x] = bo[threadIdx.x];
    __syncthreads();

    int r = blockIdx.x * blockDim.x + threadIdx.x;
    if (r >= M) return;

    const float4* hr = (const float4*)(H + (size_t)r * HID);
    float acc[NOUT];
#pragma unroll
    for (int o = 0; o < NOUT; o++) acc[o] = bs[o];

#pragma unroll
    for (int k4 = 0; k4 < 32; k4++) {
        float4 v = hr[k4];
#pragma unroll
        for (int o = 0; o < NOUT; o++) {
            acc[o] += v.x * ws[(k4 * 4 + 0) * NOUT + o];
            acc[o] += v.y * ws[(k4 * 4 + 1) * NOUT + o];
            acc[o] += v.z * ws[(k4 * 4 + 2) * NOUT + o];
            acc[o] += v.w * ws[(k4 * 4 + 3) * NOUT + o];
        }
    }
#pragma unroll
    for (int o = 0; o < NOUT; o++) out[(size_t)r * NOUT + o] = acc[o];
}

// ============================================================================
extern "C" void kernel_launch(void* const* d_in, const int* in_sizes, int n_in,
                              void* d_out, int out_size) {
    const float* x   = (const float*)d_in[0];
    const float* k0  = (const float*)d_in[1];
    const float* rk0 = (const float*)d_in[2];
    const float* b0  = (const float*)d_in[3];
    const float* k1  = (const float*)d_in[4];
    const float* rk1 = (const float*)d_in[5];
    const float* b1  = (const float*)d_in[6];
    const float* k2  = (const float*)d_in[7];
    const float* rk2 = (const float*)d_in[8];
    const float* b2  = (const float*)d_in[9];
    const float* wo  = (const float*)d_in[10];
    const float* bo  = (const float*)d_in[11];
    float* out = (float*)d_out;

    float *xwp, *h0p, *h1p;
    cudaGetSymbolAddress((void**)&xwp, g_xw);
    cudaGetSymbolAddress((void**)&h0p, g_h0);
    cudaGetSymbolAddress((void**)&h1p, g_h1);

    const int M = MROWS;
    const size_t smem = (128 * 132 + 128 * 128) * sizeof(float);  // 133 KB
    cudaFuncSetAttribute(gemm128, cudaFuncAttributeMaxDynamicSharedMemorySize,
                         (int)smem);

    dim3 ggrid(M / 128, 3);

    // Layer 0
    gemm128<<<ggrid, 256, smem>>>(x, k0, b0, b0 + 384, xwp, M);
    scan_kernel<<<BATCH, 768>>>(xwp, rk0, b0 + 384, h0p);
    // Layer 1
    gemm128<<<ggrid, 256, smem>>>(h0p, k1, b1, b1 + 384, xwp, M);
    scan_kernel<<<BATCH, 768>>>(xwp, rk1, b1 + 384, h1p);
    // Layer 2
    gemm128<<<ggrid, 256, smem>>>(h1p, k2, b2, b2 + 384, xwp, M);
    scan_kernel<<<BATCH, 768>>>(xwp, rk2, b2 + 384, h0p);
    // Output head
    outproj<<<(M + 255) / 256, 256>>>(h0p, wo, bo, out, M);
}

// round 7
// speedup vs baseline: 1.7327x; 1.7327x over previous
#include <cuda_runtime.h>
#include <cstdint>

#define HID 128
#define T_STEPS 2048
#define BATCH 64
#define NOUT 5
#define MROWS (BATCH * T_STEPS)   // 131072

// -------------------- scratch (device globals; no allocation) --------------------
__device__ float g_xw[(size_t)MROWS * 384];   // input-projection buffer
__device__ float g_h0[(size_t)MROWS * HID];   // layer output ping
__device__ float g_h1[(size_t)MROWS * HID];   // layer output pong

// -------------------- packed f32x2 helpers --------------------
__device__ __forceinline__ unsigned long long pack2(float lo, float hi) {
    unsigned long long r;
    asm("mov.b64 %0, {%1, %2};" : "=l"(r) : "f"(lo), "f"(hi));
    return r;
}
__device__ __forceinline__ void unpack2(unsigned long long v, float& lo, float& hi) {
    asm("mov.b64 {%0, %1}, %2;" : "=f"(lo), "=f"(hi) : "l"(v));
}
#define FMA2(d, a, b, c) \
    asm("fma.rn.f32x2 %0, %1, %2, %3;" : "=l"(d) : "l"(a), "l"(b), "l"(c))

// ============================================================================
// GEMM: C[M,384-tile] = A[M,128] @ W[128,384] + bias_in (+ brec for cols<256)
// grid = (M/128, 3), 256 threads, dynamic smem = As(128x132) + Bs(128x128)
// ============================================================================
__global__ __launch_bounds__(256, 1)
void gemm128(const float* __restrict__ A, const float* __restrict__ W,
             const float* __restrict__ bias, const float* __restrict__ brec,
             float* __restrict__ C, int M) {
    extern __shared__ float smem[];
    float* As = smem;              // As[k][m], pitch 132
    float* Bs = smem + 128 * 132;  // Bs[k][n], pitch 128

    const int m0 = blockIdx.x * 128;
    const int n0 = blockIdx.y * 128;
    const int tid = threadIdx.x;

    for (int idx = tid; idx < 128 * 32; idx += 256) {
        int r = idx >> 5, c4 = idx & 31;
        float4 v = *(const float4*)(A + (size_t)(m0 + r) * 128 + c4 * 4);
        As[(c4 * 4 + 0) * 132 + r] = v.x;
        As[(c4 * 4 + 1) * 132 + r] = v.y;
        As[(c4 * 4 + 2) * 132 + r] = v.z;
        As[(c4 * 4 + 3) * 132 + r] = v.w;
    }
    for (int idx = tid; idx < 128 * 32; idx += 256) {
        int k = idx >> 5, c4 = idx & 31;
        *(float4*)&Bs[k * 128 + c4 * 4] =
            *(const float4*)(W + (size_t)k * 384 + n0 + c4 * 4);
    }
    __syncthreads();

    const int tx = tid & 15, ty = tid >> 4;
    const int mr = ty * 8, nc = tx * 8;

    unsigned long long acc[8][4];
#pragma unroll
    for (int i = 0; i < 8; i++)
#pragma unroll
        for (int jj = 0; jj < 4; jj++) acc[i][jj] = 0ULL;

#pragma unroll 8
    for (int k = 0; k < 128; k++) {
        float4 a0 = *(const float4*)&As[k * 132 + mr];
        float4 a1 = *(const float4*)&As[k * 132 + mr + 4];
        ulonglong2 b0 = *(const ulonglong2*)&Bs[k * 128 + nc];
        ulonglong2 b1 = *(const ulonglong2*)&Bs[k * 128 + nc + 4];
        float av[8] = {a0.x, a0.y, a0.z, a0.w, a1.x, a1.y, a1.z, a1.w};
        unsigned long long bp[4] = {b0.x, b0.y, b1.x, b1.y};
#pragma unroll
        for (int i = 0; i < 8; i++) {
            unsigned long long ap = pack2(av[i], av[i]);
#pragma unroll
            for (int jj = 0; jj < 4; jj++) FMA2(acc[i][jj], ap, bp[jj], acc[i][jj]);
        }
    }

    float bv[8];
#pragma unroll
    for (int c = 0; c < 8; c++) {
        int n = n0 + nc + c;
        bv[c] = bias[n] + (n < 256 ? brec[n] : 0.0f);
    }

#pragma unroll
    for (int i = 0; i < 8; i++) {
        float o[8];
#pragma unroll
        for (int jj = 0; jj < 4; jj++) unpack2(acc[i][jj], o[2 * jj], o[2 * jj + 1]);
#pragma unroll
        for (int c = 0; c < 8; c++) o[c] += bv[c];
        float* cp = C + (size_t)(m0 + mr + i) * 384 + n0 + nc;
        *(float4*)cp = make_float4(o[0], o[1], o[2], o[3]);
        *(float4*)(cp + 4) = make_float4(o[4], o[5], o[6], o[7]);
    }
}

// ============================================================================
// GRU scan v5b: one CTA/batch, 384 threads; thread j owns rk column j
// (128 weights in 64 f32x2 regs). Software-pipelined broadcast LDS of h
// (FULL 32 ulonglong2 = 128 MACs — R6 bug was covering only half).
// Fast MUFU tail on 128 threads; h carried in a tail register.
// ============================================================================
__global__ __launch_bounds__(384, 1)
void scan_kernel(const float* __restrict__ xw, const float* __restrict__ rk,
                 const float* __restrict__ brec, float* __restrict__ hout) {
    const int b = blockIdx.x;
    const int j = threadIdx.x;

    __shared__ __align__(16) float h_sh[HID];
    __shared__ float g_sh[384];
    __shared__ float xh_sh[HID];

    unsigned long long w2[64];
#pragma unroll
    for (int i = 0; i < 64; i++) {
        float a0 = rk[(size_t)(2 * i) * 384 + j];
        float a1 = rk[(size_t)(2 * i + 1) * 384 + j];
        w2[i] = pack2(a0, a1);
    }

    const float brh = (j < HID) ? brec[256 + j] : 0.0f;
    float h_reg = 0.0f;
    if (j < HID) h_sh[j] = 0.0f;

    const float* xrow = xw + (size_t)b * T_STEPS * 384 + j;
    float xv0 = xrow[0];
    float xv1 = xrow[384];
    float* hrow = hout + (size_t)b * T_STEPS * HID + j;  // valid for j<128
    __syncthreads();

    for (int t = 0; t < T_STEPS; t++) {
        int tp = (t + 2 < T_STEPS) ? t + 2 : T_STEPS - 1;
        float xv2 = xrow[(size_t)tp * 384];

        // dot(h, rk[:,j]): 2-stage pipelined broadcast LDS, 32 ulonglong2
        // = 64 FMA2 = 128 MACs, two dependency chains
        const ulonglong2* hp = (const ulonglong2*)h_sh;
        unsigned long long a0 = 0ULL, a1 = 0ULL;
        ulonglong2 u0 = hp[0], u1 = hp[1];
#pragma unroll
        for (int i = 0; i < 16; i++) {
            ulonglong2 n0, n1;
            if (i < 15) { n0 = hp[2 * i + 2]; n1 = hp[2 * i + 3]; }
            FMA2(a0, u0.x, w2[4 * i + 0], a0);
            FMA2(a1, u0.y, w2[4 * i + 1], a1);
            FMA2(a0, u1.x, w2[4 * i + 2], a0);
            FMA2(a1, u1.y, w2[4 * i + 3], a1);
            u0 = n0; u1 = n1;
        }
        float l0, h0f, l1, h1f;
        unpack2(a0, l0, h0f);
        unpack2(a1, l1, h1f);
        float ri = (l0 + l1) + (h0f + h1f);

        if (j < 256) {
            g_sh[j] = ri + xv0;        // z,r: x-part (+ both biases, pre-folded)
        } else {
            g_sh[j] = ri;              // h-gate recurrent part
            xh_sh[j - 256] = xv0;      // h-gate x-part
        }
        __syncthreads();

        if (j < HID) {
            float gz = g_sh[j];
            float gr = g_sh[128 + j];
            float ph = g_sh[256 + j] + brh;
            float xh = xh_sh[j];
            float z = __fdividef(1.0f, 1.0f + __expf(-gz));
            float r = __fdividef(1.0f, 1.0f + __expf(-gr));
            float e2 = __expf(-2.0f * (xh + r * ph));
            float hh = __fdividef(2.0f, 1.0f + e2) - 1.0f;   // tanh
            float hn = z * h_reg + (1.0f - z) * hh;
            h_reg = hn;
            h_sh[j] = hn;
            hrow[(size_t)t * HID] = hn;
        }
        __syncthreads();

        xv0 = xv1;
        xv1 = xv2;
    }
}

// ============================================================================
// Output head: out[M,5] = H[M,128] @ wo[128,5] + bo
// ============================================================================
__global__ __launch_bounds__(256, 1)
void outproj(const float* __restrict__ H, const float* __restrict__ wo,
             const float* __restrict__ bo, float* __restrict__ out, int M) {
    __shared__ float ws[HID * NOUT];
    __shared__ float bs[NOUT];
    for (int i = threadIdx.x; i < HID * NOUT; i += blockDim.x) ws[i] = wo[i];
    if (threadIdx.x < NOUT) bs[threadIdx.x] = bo[threadIdx.x];
    __syncthreads();

    int r = blockIdx.x * blockDim.x + threadIdx.x;
    if (r >= M) return;

    const float4* hr = (const float4*)(H + (size_t)r * HID);
    float acc[NOUT];
#pragma unroll
    for (int o = 0; o < NOUT; o++) acc[o] = bs[o];

#pragma unroll
    for (int k4 = 0; k4 < 32; k4++) {
        float4 v = hr[k4];
#pragma unroll
        for (int o = 0; o < NOUT; o++) {
            acc[o] += v.x * ws[(k4 * 4 + 0) * NOUT + o];
            acc[o] += v.y * ws[(k4 * 4 + 1) * NOUT + o];
            acc[o] += v.z * ws[(k4 * 4 + 2) * NOUT + o];
            acc[o] += v.w * ws[(k4 * 4 + 3) * NOUT + o];
        }
    }
#pragma unroll
    for (int o = 0; o < NOUT; o++) out[(size_t)r * NOUT + o] = acc[o];
}

// ============================================================================
// Launcher: single stream, sequential (no streams/events — allocation-free).
// ============================================================================
extern "C" void kernel_launch(void* const* d_in, const int* in_sizes, int n_in,
                              void* d_out, int out_size) {
    const float* x   = (const float*)d_in[0];
    const float* k0  = (const float*)d_in[1];
    const float* rk0 = (const float*)d_in[2];
    const float* b0  = (const float*)d_in[3];
    const float* k1  = (const float*)d_in[4];
    const float* rk1 = (const float*)d_in[5];
    const float* b1  = (const float*)d_in[6];
    const float* k2  = (const float*)d_in[7];
    const float* rk2 = (const float*)d_in[8];
    const float* b2  = (const float*)d_in[9];
    const float* wo  = (const float*)d_in[10];
    const float* bo  = (const float*)d_in[11];
    float* out = (float*)d_out;

    float *xwp, *h0p, *h1p;
    cudaGetSymbolAddress((void**)&xwp, g_xw);
    cudaGetSymbolAddress((void**)&h0p, g_h0);
    cudaGetSymbolAddress((void**)&h1p, g_h1);

    const int M = MROWS;
    const size_t smem = (128 * 132 + 128 * 128) * sizeof(float);  // 133 KB
    cudaFuncSetAttribute(gemm128, cudaFuncAttributeMaxDynamicSharedMemorySize,
                         (int)smem);

    dim3 ggrid(M / 128, 3);

    // Layer 0
    gemm128<<<ggrid, 256, smem>>>(x, k0, b0, b0 + 384, xwp, M);
    scan_kernel<<<BATCH, 384>>>(xwp, rk0, b0 + 384, h0p);
    // Layer 1
    gemm128<<<ggrid, 256, smem>>>(h0p, k1, b1, b1 + 384, xwp, M);
    scan_kernel<<<BATCH, 384>>>(xwp, rk1, b1 + 384, h1p);
    // Layer 2
    gemm128<<<ggrid, 256, smem>>>(h1p, k2, b2, b2 + 384, xwp, M);
    scan_kernel<<<BATCH, 384>>>(xwp, rk2, b2 + 384, h0p);
    // Output head
    outproj<<<(MROWS + 255) / 256, 256>>>(h0p, wo, bo, out, MROWS);
}